// round 4
// baseline (speedup 1.0000x reference)
#include <cuda_runtime.h>
#include <cstdint>

#define BB 32
#define TT 512
#define KK 48
#define SROW 56              // padded row stride (words); banks (24u+j)%32 all distinct
#define NTH 192              // 6 warps
#define NB 6                 // tile ring depth
#define START_TAG 46
#define STOP_TAG 47

__device__ float g_partials[BB];
__device__ int   g_ctr = 0;

__device__ __forceinline__ float ex2f(float x) {
    float y; asm("ex2.approx.ftz.f32 %0, %1;" : "=f"(y) : "f"(x)); return y;
}
__device__ __forceinline__ float lg2f(float x) {
    float y; asm("lg2.approx.ftz.f32 %0, %1;" : "=f"(y) : "f"(x)); return y;
}
__device__ __forceinline__ void cp16(uint32_t smem, const void* g) {
    asm volatile("cp.async.cg.shared.global [%0], [%1], 16;" :: "r"(smem), "l"(g));
}
__device__ __forceinline__ void cp_commit() { asm volatile("cp.async.commit_group;"); }
__device__ __forceinline__ void cp_wait3()  { asm volatile("cp.async.wait_group 3;"); }
__device__ __forceinline__ void cp_wait4()  { asm volatile("cp.async.wait_group 4;"); }

// carry slot permutation: value for tag i lives at (i&3)*16 + (i>>2)
__device__ __forceinline__ int pslot(int i) { return (i & 3) * 16 + (i >> 2); }

extern __shared__ float smem_dyn[];

__global__ __launch_bounds__(NTH)
void crf_fwd_kernel(const float* __restrict__ feat,
                    const int*   __restrict__ targets,
                    const int*   __restrict__ lengths,
                    float*       __restrict__ out)
{
    // dynamic smem layout
    float* tile = smem_dyn;                       // NB * KK*SROW floats
    float* dshP = tile + NB * (KK * SROW);        // 2 * 64 floats
    int*   tsh  = (int*)(dshP + 2 * 64);          // TT ints

    const int b   = blockIdx.x;
    const int tid = threadIdx.x;
    const int len = lengths[b];
    const float* fb = feat + (size_t)b * TT * (KK * KK);

    for (int i = tid; i < TT; i += NTH) {
        int v = targets[b * TT + i];
        tsh[i] = (v / KK) * SROW + (v % KK);
    }

    const int l = tid & 31;
    const int w = tid >> 5;
    const int j = 8 * w + (l & 7);   // column owned by this lane
    const int u = l >> 3;            // i = u + 4*ii

    // prefetch chunks: exactly 3 per thread (576 = 3*192)
    uint32_t so[3]; size_t go[3];
    #pragma unroll
    for (int q = 0; q < 3; ++q) {
        int k = tid + q * NTH;
        so[q] = (uint32_t)((k / 12) * SROW * 4 + (k % 12) * 16);
        go[q] = (size_t)(k / 12) * KK + (size_t)(k % 12) * 4;
    }

    uint32_t sb[NB];
    #pragma unroll
    for (int n = 0; n < NB; ++n)
        sb[n] = (uint32_t)__cvta_generic_to_shared(tile + n * (KK * SROW));

    const float LOG2E = 1.4426950408889634f;
    const float LN2   = 0.6931471805599453f;

    // Prologue: issue tiles 0..4 as 5 groups
    #pragma unroll
    for (int tt = 0; tt < 5; ++tt) {
        if (tt < len) {
            const float* src = fb + (size_t)tt * (KK * KK);
            #pragma unroll
            for (int q = 0; q < 3; ++q) cp16(sb[tt] + so[q], src + go[q]);
        }
        cp_commit();
    }
    cp_wait4();            // tile 0 complete
    __syncthreads();       // tile 0 visible

    // init: S = T_0 = 2^(f0[START,:]*LOG2E), raw, into dshP[1]
    if (tid < KK) dshP[64 + pslot(tid)] = ex2f(tile[SROW * START_TAG + tid] * LOG2E);
    float gold  = 0.f;
    float refsh = 0.f;
    if (tid == 0) gold = tile[tsh[0]];

    cp_wait3();            // tile 1 complete
    __syncthreads();       // tile 1 visible

    // E for tile 1
    float E[12];
    {
        const float* fn = tile + 1 * (KK * SROW) + u * SROW + j;
        #pragma unroll
        for (int ii = 0; ii < 12; ++ii) E[ii] = ex2f(fn[SROW * 4 * ii] * LOG2E);
    }
    // issue tile 5 -> 4 groups outstanding {2,3,4,5}
    if (5 < len) {
        #pragma unroll
        for (int q = 0; q < 3; ++q) cp16(sb[5] + so[q], fb + (size_t)5 * KK * KK + go[q]);
    }
    cp_commit();

    for (int t = 1; t < len; ++t) {
        cp_wait3();          // tile t+1 complete
        __syncthreads();     // carries(t) + tile t+1 visible; ring buffer safe

        // prefetch tile t+5 into buffer (t+5)%NB (last read at iter t-1)
        {
            int tn = t + 5;
            if (tn < len) {
                const float* src = fb + (size_t)tn * (KK * KK);
                uint32_t dst = sb[tn % NB];
                #pragma unroll
                for (int q = 0; q < 3; ++q) cp16(dst + so[q], src + go[q]);
            }
            cp_commit();
        }

        const float* dr = dshP + (t & 1) * 64;
        const float  c0 = dr[0];
        const float  r  = 1.0f / c0;

        float4 A = *(const float4*)(dr + u * 16 + 0);
        float4 B = *(const float4*)(dr + u * 16 + 4);
        float4 C = *(const float4*)(dr + u * 16 + 8);

        float a0 =      E[0]  * A.x;
        float a1 =      E[1]  * A.y;
        float a2 =      E[2]  * A.z;
        float a3 =      E[3]  * A.w;
        a0 = fmaf(E[4],  B.x, a0);
        a1 = fmaf(E[5],  B.y, a1);
        a2 = fmaf(E[6],  B.z, a2);
        a3 = fmaf(E[7],  B.w, a3);
        a0 = fmaf(E[8],  C.x, a0);
        a1 = fmaf(E[9],  C.y, a1);
        a2 = fmaf(E[10], C.z, a2);
        a3 = fmaf(E[11], C.w, a3);
        float acc = (a0 + a1) + (a2 + a3);

        acc += __shfl_xor_sync(0xffffffffu, acc, 8);
        acc += __shfl_xor_sync(0xffffffffu, acc, 16);
        if (u == 0) dshP[((t + 1) & 1) * 64 + pslot(j)] = acc * r;

        if (tid == 0) {
            refsh += lg2f(c0);
            gold  += tile[(t % NB) * (KK * SROW) + tsh[t]];
        }

        // E for tile t+1 (unconditional; garbage unused at final iteration)
        {
            const float* fn = tile + ((t + 1) % NB) * (KK * SROW) + u * SROW + j;
            #pragma unroll
            for (int ii = 0; ii < 12; ++ii) E[ii] = ex2f(fn[SROW * 4 * ii] * LOG2E);
        }
    }

    __syncthreads();
    if (tid == 0) {
        float fin = (refsh + lg2f(dshP[(len & 1) * 64 + pslot(STOP_TAG)])) * LN2;
        g_partials[b] = fin - gold;
    }

    // fused deterministic batch reduction (last block)
    if (tid < 32) {
        int old = 0;
        if (tid == 0) {
            __threadfence();
            old = atomicAdd(&g_ctr, 1);
        }
        old = __shfl_sync(0xffffffffu, old, 0);
        if (old == BB - 1) {
            __threadfence();
            float v = g_partials[tid];
            #pragma unroll
            for (int o = 16; o; o >>= 1) v += __shfl_down_sync(0xffffffffu, v, o);
            if (tid == 0) { out[0] = v / (float)BB; g_ctr = 0; }
        }
    }
}

extern "C" void kernel_launch(void* const* d_in, const int* in_sizes, int n_in,
                              void* d_out, int out_size)
{
    const float* feat    = (const float*)d_in[0];
    const int*   targets = (const int*)d_in[1];
    const int*   lengths = (const int*)d_in[2];
    float*       out     = (float*)d_out;

    const int smem_bytes = NB * KK * SROW * 4 + 2 * 64 * 4 + TT * 4;  // 67072
    cudaFuncSetAttribute(crf_fwd_kernel, cudaFuncAttributeMaxDynamicSharedMemorySize, smem_bytes);
    crf_fwd_kernel<<<BB, NTH, smem_bytes>>>(feat, targets, lengths, out);
}

// round 5
// speedup vs baseline: 1.0210x; 1.0210x over previous
#include <cuda_runtime.h>
#include <cstdint>

#define BB 32
#define TT 512
#define KK 48
#define SROW 52              // row stride (words): banks 20u%32 all distinct for u=0..7
#define NTH 384              // 12 warps -> 3/SMSP, balanced MUFU
#define NB 6                 // tile ring depth
#define NCHUNK 576           // 48 rows * 12 chunks of 16 B
#define START_TAG 46
#define STOP_TAG 47

__device__ float g_partials[BB];
__device__ int   g_ctr = 0;

// volatile: pin EX2 issue before the next barrier (precompute must not sink)
__device__ __forceinline__ float ex2f_pin(float x) {
    float y; asm volatile("ex2.approx.ftz.f32 %0, %1;" : "=f"(y) : "f"(x)); return y;
}
__device__ __forceinline__ float ex2f(float x) {
    float y; asm("ex2.approx.ftz.f32 %0, %1;" : "=f"(y) : "f"(x)); return y;
}
__device__ __forceinline__ float lg2f(float x) {
    float y; asm("lg2.approx.ftz.f32 %0, %1;" : "=f"(y) : "f"(x)); return y;
}
__device__ __forceinline__ void cp16(uint32_t smem, const void* g) {
    asm volatile("cp.async.cg.shared.global [%0], [%1], 16;" :: "r"(smem), "l"(g));
}
__device__ __forceinline__ void cp_commit() { asm volatile("cp.async.commit_group;"); }
__device__ __forceinline__ void cp_wait3()  { asm volatile("cp.async.wait_group 3;"); }
__device__ __forceinline__ void cp_wait4()  { asm volatile("cp.async.wait_group 4;"); }

// carry slot permutation: tag i = u + 8*ii lives at slot u*8 + ii
__device__ __forceinline__ int pslot(int i) { return (i & 7) * 8 + (i >> 3); }

extern __shared__ float smem_dyn[];

__global__ __launch_bounds__(NTH, 1)
void crf_fwd_kernel(const float* __restrict__ feat,
                    const int*   __restrict__ targets,
                    const int*   __restrict__ lengths,
                    float*       __restrict__ out)
{
    float* tile = smem_dyn;                     // NB * KK*SROW
    float* dshP = tile + NB * (KK * SROW);      // 2 * 64
    int*   tsh  = (int*)(dshP + 2 * 64);        // TT

    const int b   = blockIdx.x;
    const int tid = threadIdx.x;
    const int len = lengths[b];
    const float* fb = feat + (size_t)b * TT * (KK * KK);

    for (int i = tid; i < TT; i += NTH) {
        int v = targets[b * TT + i];
        tsh[i] = (v / KK) * SROW + (v % KK);
    }

    // warp w owns columns 4w..4w+3: j = 4w + (l&3); i = u + 8*ii, u = l>>2
    const int l = tid & 31;
    const int w = tid >> 5;
    const int j = 4 * w + (l & 3);
    const int u = l >> 2;

    // prefetch chunks: 576 chunks over 384 threads (some threads take 2)
    const int k0 = tid;
    const int k1 = tid + NTH;
    const bool has1 = (k1 < NCHUNK);
    const uint32_t so0 = (uint32_t)((k0 / 12) * SROW * 4 + (k0 % 12) * 16);
    const size_t   go0 = (size_t)(k0 / 12) * KK + (size_t)(k0 % 12) * 4;
    const uint32_t so1 = (uint32_t)((k1 / 12) * SROW * 4 + (k1 % 12) * 16);
    const size_t   go1 = (size_t)(k1 / 12) * KK + (size_t)(k1 % 12) * 4;

    uint32_t sb[NB];
    #pragma unroll
    for (int n = 0; n < NB; ++n)
        sb[n] = (uint32_t)__cvta_generic_to_shared(tile + n * (KK * SROW));

    const float LOG2E = 1.4426950408889634f;
    const float LN2   = 0.6931471805599453f;

    // Prologue: issue tiles 0..4 as 5 groups
    #pragma unroll
    for (int tt = 0; tt < 5; ++tt) {
        if (tt < len) {
            const float* src = fb + (size_t)tt * (KK * KK);
            cp16(sb[tt] + so0, src + go0);
            if (has1) cp16(sb[tt] + so1, src + go1);
        }
        cp_commit();
    }
    cp_wait4();
    __syncthreads();       // tile 0 visible

    // init: S = 2^(f0[START,:]*log2e)  (raw linear carries), buffer 1
    if (tid < KK) dshP[64 + pslot(tid)] = ex2f(tile[SROW * START_TAG + tid] * LOG2E);
    float gold  = 0.f;
    float refsh = 0.f;
    if (tid == 0) gold = tile[tsh[0]];

    cp_wait3();
    __syncthreads();       // tile 1 visible

    // E for tile 1 (registers, pinned)
    float E[6];
    {
        const float* fn = tile + 1 * (KK * SROW) + u * SROW + j;
        #pragma unroll
        for (int ii = 0; ii < 6; ++ii)
            E[ii] = ex2f_pin(fn[SROW * 8 * ii] * LOG2E);
    }
    if (5 < len) {
        const float* src = fb + (size_t)5 * KK * KK;
        cp16(sb[5] + so0, src + go0);
        if (has1) cp16(sb[5] + so1, src + go1);
    }
    cp_commit();

    for (int t = 1; t < len; ++t) {
        cp_wait3();
        __syncthreads();     // carries(t) + tile t+1 visible

        // prefetch tile t+5 into buffer (t-1)%NB (drained)
        {
            int tn = t + 5;
            if (tn < len) {
                const float* src = fb + (size_t)tn * (KK * KK);
                uint32_t dst = sb[tn % NB];
                cp16(dst + so0, src + go0);
                if (has1) cp16(dst + so1, src + go1);
            }
            cp_commit();
        }

        const float* dr = dshP + (t & 1) * 64;
        const float  c0 = dr[0];
        const float  r  = 1.0f / c0;

        float4 A = *(const float4*)(dr + u * 8);       // carries ii=0..3
        float2 Bc = *(const float2*)(dr + u * 8 + 4);  // carries ii=4..5

        float a0 = E[0] * A.x;
        float a1 = E[1] * A.y;
        float a2 = E[2] * A.z;
        float a3 = E[3] * A.w;
        a0 = fmaf(E[4], Bc.x, a0);
        a1 = fmaf(E[5], Bc.y, a1);
        float acc = (a0 + a1) + (a2 + a3);

        acc += __shfl_xor_sync(0xffffffffu, acc, 4);
        acc += __shfl_xor_sync(0xffffffffu, acc, 8);
        acc += __shfl_xor_sync(0xffffffffu, acc, 16);
        if (u == 0) dshP[((t + 1) & 1) * 64 + pslot(j)] = acc * r;

        // E for tile t+1 (pinned pre-barrier; dead values at t = len-1 harmless)
        {
            const float* fn = tile + ((t + 1) % NB) * (KK * SROW) + u * SROW + j;
            #pragma unroll
            for (int ii = 0; ii < 6; ++ii)
                E[ii] = ex2f_pin(fn[SROW * 8 * ii] * LOG2E);
        }

        if (tid == 0) {
            refsh += lg2f(c0);
            gold  += tile[(t % NB) * (KK * SROW) + tsh[t]];
        }
    }

    __syncthreads();
    if (tid == 0) {
        float fin = (refsh + lg2f(dshP[(len & 1) * 64 + pslot(STOP_TAG)])) * LN2;
        g_partials[b] = fin - gold;
    }

    // fused deterministic batch reduction (last block)
    if (tid < 32) {
        int old = 0;
        if (tid == 0) {
            __threadfence();
            old = atomicAdd(&g_ctr, 1);
        }
        old = __shfl_sync(0xffffffffu, old, 0);
        if (old == BB - 1) {
            __threadfence();
            float v = g_partials[tid];
            #pragma unroll
            for (int o = 16; o; o >>= 1) v += __shfl_down_sync(0xffffffffu, v, o);
            if (tid == 0) { out[0] = v / (float)BB; g_ctr = 0; }
        }
    }
}

extern "C" void kernel_launch(void* const* d_in, const int* in_sizes, int n_in,
                              void* d_out, int out_size)
{
    const float* feat    = (const float*)d_in[0];
    const int*   targets = (const int*)d_in[1];
    const int*   lengths = (const int*)d_in[2];
    float*       out     = (float*)d_out;

    const int smem_bytes = NB * KK * SROW * 4 + 2 * 64 * 4 + TT * 4;  // 62464
    cudaFuncSetAttribute(crf_fwd_kernel, cudaFuncAttributeMaxDynamicSharedMemorySize, smem_bytes);
    crf_fwd_kernel<<<BB, NTH, smem_bytes>>>(feat, targets, lengths, out);
}

// round 6
// speedup vs baseline: 1.8222x; 1.7846x over previous
#include <cuda_runtime.h>
#include <cstdint>

#define BB 32
#define TT 512
#define KK 48
#define SROW 56              // banks (24u + j) % 32 all distinct for u=0..3, j=0..7
#define TILESZ (KK * SROW)
#define NTH 192              // 6 warps
#define NB 6                 // tile ring depth
#define NCHUNK 576           // 48 rows * 12 chunks of 16 B  (= 3 per thread)
#define CARRYSZ 80           // padded carry buffer (slot = (i&3)*20 + (i>>2))
#define START_TAG 46
#define STOP_TAG 47

__device__ float g_partials[BB];
__device__ int   g_ctr = 0;

__device__ __forceinline__ float ex2f_pin(float x) {
    float y; asm volatile("ex2.approx.ftz.f32 %0, %1;" : "=f"(y) : "f"(x)); return y;
}
__device__ __forceinline__ float ex2f(float x) {
    float y; asm("ex2.approx.ftz.f32 %0, %1;" : "=f"(y) : "f"(x)); return y;
}
__device__ __forceinline__ float lg2f(float x) {
    float y; asm("lg2.approx.ftz.f32 %0, %1;" : "=f"(y) : "f"(x)); return y;
}
__device__ __forceinline__ void cp16(uint32_t smem, const void* g) {
    asm volatile("cp.async.cg.shared.global [%0], [%1], 16;" :: "r"(smem), "l"(g));
}
__device__ __forceinline__ void cp_commit() { asm volatile("cp.async.commit_group;"); }
__device__ __forceinline__ void cp_wait3()  { asm volatile("cp.async.wait_group 3;"); }
__device__ __forceinline__ void cp_wait4()  { asm volatile("cp.async.wait_group 4;"); }

// tag i = u + 4*ii  ->  slot u*20 + ii  (conflict-free, 16B-aligned per u)
__device__ __forceinline__ int pslot(int i) { return (i & 3) * 20 + (i >> 2); }

extern __shared__ float smem_dyn[];

__global__ __launch_bounds__(NTH, 1)
void crf_fwd_kernel(const float* __restrict__ feat,
                    const int*   __restrict__ targets,
                    const int*   __restrict__ lengths,
                    float*       __restrict__ out)
{
    float* tile = smem_dyn;                     // NB * TILESZ
    float* dshP = tile + NB * TILESZ;           // 2 * CARRYSZ
    int*   tsh  = (int*)(dshP + 2 * CARRYSZ);   // TT

    const int b   = blockIdx.x;
    const int tid = threadIdx.x;
    const int len = lengths[b];
    const float* fb = feat + (size_t)b * TT * (KK * KK);

    for (int i = tid; i < TT; i += NTH) {
        int v = targets[b * TT + i];
        tsh[i] = (v / KK) * SROW + (v % KK);
    }

    // warp w owns columns 8w..8w+7: j = 8w + (l&7); i = u + 4*ii, u = l>>3
    const int l = tid & 31;
    const int w = tid >> 5;
    const int j = 8 * w + (l & 7);
    const int u = l >> 3;

    // prefetch chunks: exactly 3 per thread
    uint32_t so[3]; size_t go[3];
    #pragma unroll
    for (int q = 0; q < 3; ++q) {
        int k = tid + q * NTH;
        so[q] = (uint32_t)((k / 12) * SROW * 4 + (k % 12) * 16);
        go[q] = (size_t)(k / 12) * KK + (size_t)(k % 12) * 4;
    }

    uint32_t sb[NB];
    #pragma unroll
    for (int n = 0; n < NB; ++n)
        sb[n] = (uint32_t)__cvta_generic_to_shared(tile + n * TILESZ);

    const float LOG2E = 1.4426950408889634f;
    const float LN2   = 0.6931471805599453f;

    // Prologue: issue tiles 0..4 as 5 groups
    #pragma unroll
    for (int tt = 0; tt < 5; ++tt) {
        if (tt < len) {
            const float* src = fb + (size_t)tt * (KK * KK);
            #pragma unroll
            for (int q = 0; q < 3; ++q) cp16(sb[tt] + so[q], src + go[q]);
        }
        cp_commit();
    }
    cp_wait4();
    __syncthreads();       // tile 0 visible

    // init: raw linear carries S = 2^(f0[START,:]*log2e), buffer 1
    if (tid < KK) dshP[CARRYSZ + pslot(tid)] = ex2f(tile[SROW * START_TAG + tid] * LOG2E);
    float gold = 0.f;
    int   eacc = 0;                      // accumulated power-of-two exponents
    if (tid == 0) gold = tile[tsh[0]];

    cp_wait3();
    __syncthreads();       // tile 1 visible

    // E for tile 1
    float E[12];
    {
        const float* fn = tile + 1 * TILESZ + u * SROW + j;
        #pragma unroll
        for (int ii = 0; ii < 12; ++ii)
            E[ii] = ex2f_pin(fn[SROW * 4 * ii] * LOG2E);
    }
    if (5 < len) {
        const float* src = fb + (size_t)5 * (KK * KK);
        #pragma unroll
        for (int q = 0; q < 3; ++q) cp16(sb[5] + so[q], src + go[q]);
    }
    cp_commit();

    int cur = 1;   // t % NB
    int pfb = 0;   // (t+5) % NB
    for (int t = 1; t < len; ++t) {
        cp_wait3();
        __syncthreads();     // carries(t) + tile t+1 visible; buffer pfb drained

        // prefetch tile t+5
        {
            int tn = t + 5;
            if (tn < len) {
                const float* src = fb + (size_t)tn * (KK * KK);
                uint32_t dst = sb[pfb];
                #pragma unroll
                for (int q = 0; q < 3; ++q) cp16(dst + so[q], src + go[q]);
            }
            cp_commit();
        }

        const float* dr = dshP + (t & 1) * CARRYSZ;
        const float  c0 = dr[0];
        // exact power-of-two renormalization: r = 2^-(ilogb(c0))
        const uint32_t cb = __float_as_uint(c0);
        const int      be = (int)(cb >> 23);
        const float    r  = __uint_as_float((uint32_t)(254 - be) << 23);

        float4 A = *(const float4*)(dr + u * 20 + 0);
        float4 B = *(const float4*)(dr + u * 20 + 4);
        float4 C = *(const float4*)(dr + u * 20 + 8);

        float a0 = E[0] * A.x;
        float a1 = E[1] * A.y;
        a0 = fmaf(E[2],  A.z, a0);
        a1 = fmaf(E[3],  A.w, a1);
        a0 = fmaf(E[4],  B.x, a0);
        a1 = fmaf(E[5],  B.y, a1);
        a0 = fmaf(E[6],  B.z, a0);
        a1 = fmaf(E[7],  B.w, a1);
        a0 = fmaf(E[8],  C.x, a0);
        a1 = fmaf(E[9],  C.y, a1);
        a0 = fmaf(E[10], C.z, a0);
        a1 = fmaf(E[11], C.w, a1);
        float acc = a0 + a1;

        if (tid == 0) {
            eacc += be - 127;
            gold += tile[cur * TILESZ + tsh[t]];
        }

        // E for tile t+1 — issued here so EX2s drain under the shfl latency.
        // (volatile keeps them ordered before next iteration's consumers)
        {
            const float* fn = tile + ((cur + 1 == NB) ? 0 : cur + 1) * TILESZ + u * SROW + j;
            #pragma unroll
            for (int ii = 0; ii < 12; ++ii)
                E[ii] = ex2f_pin(fn[SROW * 4 * ii] * LOG2E);
        }

        acc += __shfl_xor_sync(0xffffffffu, acc, 8);
        acc += __shfl_xor_sync(0xffffffffu, acc, 16);
        if (u == 0) dshP[((t + 1) & 1) * CARRYSZ + pslot(j)] = acc * r;

        if (++cur == NB) cur = 0;
        if (++pfb == NB) pfb = 0;
    }

    __syncthreads();
    if (tid == 0) {
        float fin = ((float)eacc + lg2f(dshP[(len & 1) * CARRYSZ + pslot(STOP_TAG)])) * LN2;
        g_partials[b] = fin - gold;
    }

    // fused deterministic batch reduction (last block)
    if (tid < 32) {
        int old = 0;
        if (tid == 0) {
            __threadfence();
            old = atomicAdd(&g_ctr, 1);
        }
        old = __shfl_sync(0xffffffffu, old, 0);
        if (old == BB - 1) {
            __threadfence();
            float v = g_partials[tid];
            #pragma unroll
            for (int o = 16; o; o >>= 1) v += __shfl_down_sync(0xffffffffu, v, o);
            if (tid == 0) { out[0] = v / (float)BB; g_ctr = 0; }
        }
    }
}

extern "C" void kernel_launch(void* const* d_in, const int* in_sizes, int n_in,
                              void* d_out, int out_size)
{
    const float* feat    = (const float*)d_in[0];
    const int*   targets = (const int*)d_in[1];
    const int*   lengths = (const int*)d_in[2];
    float*       out     = (float*)d_out;

    const int smem_bytes = NB * TILESZ * 4 + 2 * CARRYSZ * 4 + TT * 4;  // ~67 KB
    cudaFuncSetAttribute(crf_fwd_kernel, cudaFuncAttributeMaxDynamicSharedMemorySize, smem_bytes);
    crf_fwd_kernel<<<BB, NTH, smem_bytes>>>(feat, targets, lengths, out);
}